// round 15
// baseline (speedup 1.0000x reference)
#include <cuda_runtime.h>
#include <cuda_bf16.h>
#include <cstdint>

#define I_DIM 2048
#define H_DIM 96
#define B_DIM 64
#define T_DIM 512

typedef unsigned long long ull;

// ============================ generic helpers ==============================

__device__ __forceinline__ void fma2(ull &d, ull a, ull b) {
    asm("fma.rn.f32x2 %0, %1, %2, %0;" : "+l"(d) : "l"(a), "l"(b));
}
__device__ __forceinline__ ull pack2(float lo, float hi) {
    ull v; asm("mov.b64 %0, {%1, %2};" : "=l"(v) : "f"(lo), "f"(hi)); return v;
}
__device__ __forceinline__ float fast_tanh(float x) {
    float e = __expf(2.0f * x);
    return 1.0f - __fdividef(2.0f, e + 1.0f);
}
__device__ __forceinline__ uint32_t smem_u32(const void* p) {
    uint32_t a;
    asm("{ .reg .u64 t; cvta.to.shared.u64 t, %1; cvt.u32.u64 %0, t; }" : "=r"(a) : "l"(p));
    return a;
}
__device__ __forceinline__ void lds_v2u64(ull &x, ull &y, uint32_t a) {
    asm volatile("ld.shared.v2.b64 {%0,%1}, [%2];" : "=l"(x), "=l"(y) : "r"(a));
}
__device__ __forceinline__ void sts_f32(uint32_t a, float v) {
    asm volatile("st.shared.f32 [%0], %1;" :: "r"(a), "f"(v) : "memory");
}
__device__ __forceinline__ void sts_u32(uint32_t a, uint32_t v) {
    asm volatile("st.shared.u32 [%0], %1;" :: "r"(a), "r"(v) : "memory");
}
__device__ __forceinline__ void sts_u16(uint32_t a, uint16_t v) {
    asm volatile("st.shared.u16 [%0], %1;" :: "r"(a), "h"(v) : "memory");
}
__device__ __forceinline__ float lds_f32(uint32_t a) {
    float v; asm volatile("ld.shared.f32 %0, [%1];" : "=f"(v) : "r"(a)); return v;
}
__device__ __forceinline__ float hsum4x(ull a0, ull a1, ull a2, ull a3) {
    ull t, u, v;
    asm("add.rn.f32x2 %0, %1, %2;" : "=l"(t) : "l"(a0), "l"(a1));
    asm("add.rn.f32x2 %0, %1, %2;" : "=l"(u) : "l"(a2), "l"(a3));
    asm("add.rn.f32x2 %0, %1, %2;" : "=l"(v) : "l"(t), "l"(u));
    float lo, hi; asm("mov.b64 {%0,%1}, %2;" : "=f"(lo), "=f"(hi) : "l"(v));
    return lo + hi;
}
// cross-CTA flags (gpu scope)
__device__ __forceinline__ int ldg_acq(const int* p) {
    int v; asm volatile("ld.global.acquire.gpu.u32 %0, [%1];" : "=r"(v) : "l"(p) : "memory");
    return v;
}
__device__ __forceinline__ void stg_rel(int* p, int v) {
    asm volatile("membar.gl;" ::: "memory");
    asm volatile("st.global.release.gpu.u32 [%0], %1;" :: "l"(p), "r"(v) : "memory");
}
#define GPOLL(p, val) do { \
    if (ldg_acq(p) < (val)) { while (ldg_acq(p) < (val)) __nanosleep(64); } \
} while (0)
// intra-CTA flags (smem, cta scope)
__device__ __forceinline__ int lds_acq_cta(uint32_t a) {
    int v; asm volatile("ld.acquire.cta.shared.u32 %0, [%1];" : "=r"(v) : "r"(a) : "memory");
    return v;
}
__device__ __forceinline__ void sts_rel_cta(uint32_t a, int v) {
    asm volatile("st.release.cta.shared.u32 [%0], %1;" :: "r"(a), "r"(v) : "memory");
}
#define SSPIN(addr, val) do { \
    if (lds_acq_cta(addr) < (val)) { while (lds_acq_cta(addr) < (val)) __nanosleep(32); } \
} while (0)

// 96-float dot: broadcast LDS from src, weights in wreg[48] (ull pairs).
__device__ __forceinline__ float dot96(uint32_t src, const ull* wreg) {
    ull a0 = 0, a1 = 0, a2 = 0, a3 = 0;
    #pragma unroll
    for (int k = 0; k < 24; k++) {
        ull vx, vy; lds_v2u64(vx, vy, src + 16 * k);
        if (k & 1) { fma2(a2, wreg[2 * k], vx); fma2(a3, wreg[2 * k + 1], vy); }
        else       { fma2(a0, wreg[2 * k], vx); fma2(a1, wreg[2 * k + 1], vy); }
    }
    return hsum4x(a0, a1, a2, a3);
}

// ======================= mma.sync / ldmatrix helpers =======================

__device__ __forceinline__ void ldsm_x4(uint32_t &r0, uint32_t &r1, uint32_t &r2,
                                        uint32_t &r3, uint32_t addr) {
    asm volatile("ldmatrix.sync.aligned.m8n8.x4.shared.b16 {%0,%1,%2,%3}, [%4];"
                 : "=r"(r0), "=r"(r1), "=r"(r2), "=r"(r3) : "r"(addr));
}
__device__ __forceinline__ void ldsm_x2(uint32_t &r0, uint32_t &r1, uint32_t addr) {
    asm volatile("ldmatrix.sync.aligned.m8n8.x2.shared.b16 {%0,%1}, [%2];"
                 : "=r"(r0), "=r"(r1) : "r"(addr));
}
__device__ __forceinline__ void mma16816(float* c, const uint32_t* a, const uint32_t* b) {
    asm volatile("mma.sync.aligned.m16n8k16.row.col.f32.bf16.bf16.f32 "
                 "{%0,%1,%2,%3}, {%4,%5,%6,%7}, {%8,%9}, {%0,%1,%2,%3};"
                 : "+f"(c[0]), "+f"(c[1]), "+f"(c[2]), "+f"(c[3])
                 : "r"(a[0]), "r"(a[1]), "r"(a[2]), "r"(a[3]), "r"(b[0]), "r"(b[1]));
}
__device__ __forceinline__ void cvt_hilo(float4 v, uint2 &hp, uint2 &lp) {
    __nv_bfloat162 h0 = __float22bfloat162_rn(make_float2(v.x, v.y));
    __nv_bfloat162 h1 = __float22bfloat162_rn(make_float2(v.z, v.w));
    float2 f0 = __bfloat1622float2(h0), f1 = __bfloat1622float2(h1);
    __nv_bfloat162 l0 = __float22bfloat162_rn(make_float2(v.x - f0.x, v.y - f0.y));
    __nv_bfloat162 l1 = __float22bfloat162_rn(make_float2(v.z - f1.x, v.w - f1.y));
    hp = make_uint2(*(uint32_t*)&h0, *(uint32_t*)&h1);
    lp = make_uint2(*(uint32_t*)&l0, *(uint32_t*)&l1);
}
__device__ __forceinline__ void cvt_hilo2(float2 v, uint32_t &hp, uint32_t &lp) {
    __nv_bfloat162 h = __float22bfloat162_rn(v);
    float2 f = __bfloat1622float2(h);
    __nv_bfloat162 l = __float22bfloat162_rn(make_float2(v.x - f.x, v.y - f.y));
    hp = *(uint32_t*)&h; lp = *(uint32_t*)&l;
}
__device__ __forceinline__ void cvt_hilo1(float v, uint16_t &hb, uint16_t &lb) {
    __nv_bfloat16 h = __float2bfloat16(v);
    float f = __bfloat162float(h);
    __nv_bfloat16 l = __float2bfloat16(v - f);
    hb = *(uint16_t*)&h; lb = *(uint16_t*)&l;
}

// P-group building blocks -----------------------------------------------------

__device__ __forceinline__ void fill_afrags(const float* wih, int wp, int lane,
                                            uint32_t (&aH)[2][6][4], uint32_t (&aL)[2][6][4]) {
    const int q = lane >> 2, kq = 2 * (lane & 3);
    #pragma unroll
    for (int mt = 0; mt < 2; ++mt) {
        const int r0 = 32 * wp + 16 * mt + q;
        #pragma unroll
        for (int kc = 0; kc < 6; ++kc) {
            const int k0 = 16 * kc + kq;
            float2 v00 = *(const float2*)(wih + r0 * H_DIM + k0);
            float2 v10 = *(const float2*)(wih + (r0 + 8) * H_DIM + k0);
            float2 v01 = *(const float2*)(wih + r0 * H_DIM + k0 + 8);
            float2 v11 = *(const float2*)(wih + (r0 + 8) * H_DIM + k0 + 8);
            cvt_hilo2(v00, aH[mt][kc][0], aL[mt][kc][0]);
            cvt_hilo2(v10, aH[mt][kc][1], aL[mt][kc][1]);
            cvt_hilo2(v01, aH[mt][kc][2], aL[mt][kc][2]);
            cvt_hilo2(v11, aH[mt][kc][3], aL[mt][kc][3]);
        }
    }
}
__device__ __forceinline__ void pack8(uint32_t buf, int jj, const float* v8) {
    #pragma unroll
    for (int r = 0; r < 8; r++) {
        uint16_t hbv, lbv; cvt_hilo1(v8[r], hbv, lbv);
        sts_u16(buf + (uint32_t)(r * 208 + jj * 2), hbv);
        sts_u16(buf + 1664 + (uint32_t)(r * 208 + jj * 2), lbv);
    }
}
__device__ __forceinline__ void mma_block(float (&cfr)[2][4], uint32_t buf, uint32_t bladdr,
                                          const uint32_t (&aH)[2][6][4],
                                          const uint32_t (&aL)[2][6][4]) {
    #pragma unroll
    for (int kc = 0; kc < 6; ++kc) {
        uint32_t bh[2], bl[2];
        ldsm_x2(bh[0], bh[1], buf + bladdr + kc * 32);
        ldsm_x2(bl[0], bl[1], buf + 1664 + bladdr + kc * 32);
        #pragma unroll
        for (int mt = 0; mt < 2; ++mt) {
            mma16816(cfr[mt], aH[mt][kc], bh);
            mma16816(cfr[mt], aH[mt][kc], bl);
            mma16816(cfr[mt], aL[mt][kc], bh);
        }
    }
}
// scalar stores (36B row stride is 4-mod-8 on odd rows)
__device__ __forceinline__ void store_cfr(const float (&cfr)[2][4], uint32_t ublk,
                                          int wp, int lane) {
    #pragma unroll
    for (int mt = 0; mt < 2; ++mt) {
        const int row = 32 * wp + 16 * mt + (lane >> 2);
        const uint32_t a0 = ublk + (uint32_t)(row * 36 + (lane & 3) * 8);
        sts_f32(a0, cfr[mt][0]);
        sts_f32(a0 + 4, cfr[mt][1]);
        sts_f32(a0 + 288, cfr[mt][2]);
        sts_f32(a0 + 292, cfr[mt][3]);
    }
}

// ===================== global scratch (no allocations) =====================
__device__ float g_xproj[(size_t)B_DIM * T_DIM * H_DIM];
__device__ float g_h0[(size_t)B_DIM * T_DIM * H_DIM];
__device__ int   g_prog[B_DIM];     // l0 step progress; reset by P1 (reader)
__device__ int   g_xflag[256];      // xproj tile flags [tb*64+b]; reset by l0

// ===========================================================================
// Single fused kernel. Grid 148 (one CTA/SM), 384 threads:
//  Blocks 0-63:    layer 0, batch b = bid. R threads 0-95, bar 1.
//                  Waits on g_xflag tile flags; resets them at end.
//  Blocks 64-127:  layers 1+2, batch b = bid-64 (P1/P2/R2/R1, serial R groups
//                  on the highest warp ids). P1 resets g_prog[b] at end.
//  Blocks 128-147: xproj GEMM workers (20). Each processes tiles
//                  g = w, w+20, ... < 256 in (tb-major) order; tile g covers
//                  batch g&63, steps [(g>>6)*128, +128). Publishes g_xflag[g].
//                  Workers never wait -> pipeline deadlock-free.
// ===========================================================================
#define ROWB 80
// gemm-worker smem layout (within the same dynamic buffer)
#define SM_BIAS 0
#define SM_AHI  512
#define SM_ALO  (512 + 10240)
#define SM_BHI  (512 + 20480)
#define SM_BLO  (512 + 20480 + 7680)
// l12 smem layout
#define L_RING 0
#define L_H2   12288
#define L_U1   13056
#define L_U2   23424
#define L_BS1  33792
#define L_BS2  40448
#define L_SRED 47104
#define L_CNT  47488
#define SCAN_SMEM 47616
#define U_STRIDE 3456

#define BARR1() asm volatile("bar.sync 1, 96;" ::: "memory")
#define BARR2() asm volatile("bar.sync 2, 96;" ::: "memory")
#define P1BAR() asm volatile("bar.sync 4, 96;" ::: "memory")
#define P2BAR() asm volatile("bar.sync 5, 96;" ::: "memory")

__global__ __launch_bounds__(384, 1) void rnn_all(
    const float* __restrict__ x,
    const float* __restrict__ wih0, const float* __restrict__ whh0,
    const float* __restrict__ bih0, const float* __restrict__ bhh0,
    const float* __restrict__ wih1, const float* __restrict__ whh1,
    const float* __restrict__ bih1, const float* __restrict__ bhh1,
    const float* __restrict__ wih2, const float* __restrict__ whh2,
    const float* __restrict__ bih2, const float* __restrict__ bhh2,
    const float* __restrict__ fcw,  const float* __restrict__ fcb,
    float* __restrict__ out)
{
    extern __shared__ char dyns[];
    const uint32_t dsm = smem_u32(dyns);
    const int tid = threadIdx.x;
    const int lane = tid & 31;

    if (blockIdx.x >= 128) {
        // ======================= GEMM WORKERS =======================
        if (tid >= 256) return;
        const int wkr = blockIdx.x - 128;
        const int warp = tid >> 5;
        const int m_warp = (warp & 3) * 32;
        const int n_warp = (warp >> 2) * 48;
        float* sbias = (float*)(dyns + SM_BIAS);
        if (tid < H_DIM) sbias[tid] = __ldg(bih0 + tid);

        const int g = lane >> 3, r = lane & 7;
        const uint32_t lane_off = (uint32_t)((((g & 1) << 3) + r) * ROWB + ((g >> 1) << 4));
        const uint32_t aHiB = dsm + SM_AHI + (uint32_t)m_warp * ROWB + lane_off;
        const uint32_t aLoB = dsm + SM_ALO + (uint32_t)m_warp * ROWB + lane_off;
        const uint32_t bHiB = dsm + SM_BHI + (uint32_t)n_warp * ROWB + lane_off;
        const uint32_t bLoB = dsm + SM_BLO + (uint32_t)n_warp * ROWB + lane_off;

        float4 sa[4], sw[3];
        auto load_stage = [&](const float* Xb, int k0) {
            #pragma unroll
            for (int it = 0; it < 4; ++it) {
                int f = tid + it * 256;
                sa[it] = *(const float4*)(Xb + (size_t)(f >> 3) * I_DIM + k0 + ((f & 7) << 2));
            }
            #pragma unroll
            for (int it = 0; it < 3; ++it) {
                int f = tid + it * 256;
                sw[it] = *(const float4*)(wih0 + (size_t)(f >> 3) * I_DIM + k0 + ((f & 7) << 2));
            }
        };
        auto store_stage = [&]() {
            #pragma unroll
            for (int it = 0; it < 4; ++it) {
                int f = tid + it * 256;
                int off = (f >> 3) * ROWB + ((f & 7) << 3);
                uint2 hp, lp; cvt_hilo(sa[it], hp, lp);
                *(uint2*)(dyns + SM_AHI + off) = hp;
                *(uint2*)(dyns + SM_ALO + off) = lp;
            }
            #pragma unroll
            for (int it = 0; it < 3; ++it) {
                int f = tid + it * 256;
                int off = (f >> 3) * ROWB + ((f & 7) << 3);
                uint2 hp, lp; cvt_hilo(sw[it], hp, lp);
                *(uint2*)(dyns + SM_BHI + off) = hp;
                *(uint2*)(dyns + SM_BLO + off) = lp;
            }
        };

        __syncthreads();
        for (int gtile = wkr; gtile < 256; gtile += 20) {
            const int tb = gtile >> 6, bb = gtile & 63;
            const int rowbase = bb * T_DIM + tb * 128;
            const float* Xb = x + (size_t)rowbase * I_DIM;

            float acc[2][6][4];
            #pragma unroll
            for (int mt = 0; mt < 2; mt++)
                #pragma unroll
                for (int nt = 0; nt < 6; nt++)
                    #pragma unroll
                    for (int i = 0; i < 4; i++) acc[mt][nt][i] = 0.f;

            load_stage(Xb, 0);
            store_stage();
            __syncthreads();

            const int NC = I_DIM / 32;
            for (int c = 0; c < NC; ++c) {
                if (c + 1 < NC) load_stage(Xb, (c + 1) * 32);
                #pragma unroll
                for (int s = 0; s < 2; ++s) {
                    uint32_t ah[2][4], al[2][4], bh[6][2], bl[6][2];
                    #pragma unroll
                    for (int mt = 0; mt < 2; ++mt) {
                        ldsm_x4(ah[mt][0], ah[mt][1], ah[mt][2], ah[mt][3], aHiB + mt * (16 * ROWB) + s * 32);
                        ldsm_x4(al[mt][0], al[mt][1], al[mt][2], al[mt][3], aLoB + mt * (16 * ROWB) + s * 32);
                    }
                    #pragma unroll
                    for (int np = 0; np < 3; ++np) {
                        uint32_t r0, r1, r2, r3;
                        ldsm_x4(r0, r1, r2, r3, bHiB + np * (16 * ROWB) + s * 32);
                        bh[2 * np][0] = r0; bh[2 * np + 1][0] = r1;
                        bh[2 * np][1] = r2; bh[2 * np + 1][1] = r3;
                        ldsm_x4(r0, r1, r2, r3, bLoB + np * (16 * ROWB) + s * 32);
                        bl[2 * np][0] = r0; bl[2 * np + 1][0] = r1;
                        bl[2 * np][1] = r2; bl[2 * np + 1][1] = r3;
                    }
                    #pragma unroll
                    for (int mt = 0; mt < 2; ++mt)
                        #pragma unroll
                        for (int nt = 0; nt < 6; ++nt) {
                            mma16816(acc[mt][nt], ah[mt], bh[nt]);
                            mma16816(acc[mt][nt], ah[mt], bl[nt]);
                            mma16816(acc[mt][nt], al[mt], bh[nt]);
                        }
                }
                __syncthreads();
                if (c + 1 < NC) { store_stage(); }
                __syncthreads();
            }

            #pragma unroll
            for (int nt = 0; nt < 6; ++nt) {
                int col = n_warp + nt * 8 + (lane & 3) * 2;
                float b0 = sbias[col], b1 = sbias[col + 1];
                #pragma unroll
                for (int mt = 0; mt < 2; ++mt) {
                    int row0 = rowbase + m_warp + mt * 16 + (lane >> 2);
                    float2 v0 = make_float2(acc[mt][nt][0] + b0, acc[mt][nt][1] + b1);
                    float2 v1 = make_float2(acc[mt][nt][2] + b0, acc[mt][nt][3] + b1);
                    *(float2*)(g_xproj + (size_t)row0 * H_DIM + col) = v0;
                    *(float2*)(g_xproj + (size_t)(row0 + 8) * H_DIM + col) = v1;
                }
            }
            __syncthreads();
            if (tid == 0) stg_rel(&g_xflag[gtile], 1);
        }
        return;
    }

    if (blockIdx.x < 64) {
        // ============================ LAYER 0 ============================
        const int b = blockIdx.x;
        const size_t soff = (size_t)b * T_DIM * H_DIM;
        if (tid < 192) sts_f32(dsm + tid * 4, 0.f);
        __syncthreads();
        if (tid >= 96) return;

        const int j = tid;
        ull w[48];
        {
            const float* wr = whh0 + j * H_DIM;
            #pragma unroll
            for (int q = 0; q < 48; q++) w[q] = pack2(__ldg(wr + 2 * q), __ldg(wr + 2 * q + 1));
        }
        const float bias = __ldg(bhh0 + j);
        const float* xpp = g_xproj + soff + j;
        float* outstream = g_h0 + soff;
        int* flag = &g_prog[b];

        int tcur = 0;
        GPOLL(&g_xflag[b], 1);                              // tile tb=0 ready
        float xc[8], xn[8];
        #pragma unroll
        for (int r = 0; r < 8; r++) xc[r] = __ldg(xpp + (size_t)r * H_DIM);
        #pragma unroll
        for (int r = 0; r < 8; r++) xn[r] = __ldg(xpp + (size_t)(8 + r) * H_DIM);

        const uint32_t dst_j = dsm + (uint32_t)(j * 4);
        for (int ow = 0; ow < 64; ++ow) {
            #pragma unroll
            for (int si = 0; si < 8; ++si) {
                const int v = 8 * ow + si;
                float d = dot96(dsm + (uint32_t)(((si & 1) ^ 1) * 384), w);
                float hv = fast_tanh(d + xc[si] + bias);
                sts_f32(dst_j + (uint32_t)((si & 1) * 384), hv);
                outstream[(size_t)v * H_DIM + j] = hv;
                BARR1();
            }
            if (j == 0) stg_rel(flag, 8 * ow + 8);
            // prefetch horizon: steps 8ow+16..23 -> tile (8ow+23)/128
            int tn = (8 * ow + 23) >> 7; if (tn > 3) tn = 3;
            if (tn > tcur) { GPOLL(&g_xflag[tn * 64 + b], 1); tcur = tn; }
            #pragma unroll
            for (int r = 0; r < 8; r++) xc[r] = xn[r];
            #pragma unroll
            for (int r = 0; r < 8; r++) {
                int t = 8 * ow + 16 + r; if (t > T_DIM - 1) t = T_DIM - 1;
                xn[r] = __ldg(xpp + (size_t)t * H_DIM);
            }
        }
        // reset tile flags (this block is their only reader) for graph replay
        if (j == 0) {
            stg_rel(&g_xflag[b], 0);
            stg_rel(&g_xflag[64 + b], 0);
            stg_rel(&g_xflag[128 + b], 0);
            stg_rel(&g_xflag[192 + b], 0);
        }
        return;
    }

    // ============================ LAYERS 1+2 ============================
    const int b = blockIdx.x - 64;
    const size_t soff = (size_t)b * T_DIM * H_DIM;
    const uint32_t ring = dsm + L_RING, hb2 = dsm + L_H2;
    const uint32_t u1 = dsm + L_U1, u2 = dsm + L_U2;
    const uint32_t c_r1 = dsm + L_CNT,     c_p2 = dsm + L_CNT + 4;
    const uint32_t c_u1 = dsm + L_CNT + 8, c_r2 = dsm + L_CNT + 12;
    const uint32_t c_u2 = dsm + L_CNT + 16;

    for (int i = tid; i < (12288 + 768) / 4; i += 384) sts_f32(dsm + (uint32_t)(i * 4), 0.f);
    if (tid < 5) sts_u32(dsm + L_CNT + (uint32_t)(tid * 4), 0u);
    __syncthreads();

    if (tid < 96) {
        // --------- P1 (wid 0-2): u1 = Wih1 x h0-stream ---------
        const int jj = tid;
        const int wp = jj >> 5;
        uint32_t aH[2][6][4], aL[2][6][4];
        fill_afrags(wih1, wp, lane, aH, aL);
        const uint32_t bladdr = (uint32_t)((lane & 7) * 208 + ((lane >> 3) & 1) * 16);
        const uint32_t b0 = dsm + L_BS1, b1 = dsm + L_BS1 + 3328;
        const float* instream = g_h0 + soff;
        int* inflag = &g_prog[b];
        float t8[8];

        GPOLL(inflag, 16);
        #pragma unroll
        for (int r = 0; r < 8; r++) t8[r] = instream[(size_t)r * H_DIM + jj];
        pack8(b0, jj, t8); P1BAR();
        { float cfr[2][4] = {{0,0,0,0},{0,0,0,0}};
          mma_block(cfr, b0, bladdr, aH, aL); store_cfr(cfr, u1, wp, lane); }
        #pragma unroll
        for (int r = 0; r < 8; r++) t8[r] = instream[(size_t)(8 + r) * H_DIM + jj];
        pack8(b1, jj, t8); P1BAR();
        { float cfr[2][4] = {{0,0,0,0},{0,0,0,0}};
          mma_block(cfr, b1, bladdr, aH, aL); store_cfr(cfr, u1 + U_STRIDE, wp, lane); }
        P1BAR();
        if (tid == 0) sts_rel_cta(c_u1, 2);

        for (int ow = 0; ow < 62; ++ow) {
            const int s0 = 8 * ow + 16;
            GPOLL(inflag, s0 + 8);
            #pragma unroll
            for (int r = 0; r < 8; r++) t8[r] = instream[(size_t)(s0 + r) * H_DIM + jj];
            const uint32_t buf = (ow & 1) ? b1 : b0;
            pack8(buf, jj, t8); P1BAR();
            float cfr[2][4] = {{0,0,0,0},{0,0,0,0}};
            mma_block(cfr, buf, bladdr, aH, aL);
            SSPIN(c_r1, 8 * ow);
            store_cfr(cfr, u1 + (uint32_t)(((ow + 2) % 3) * U_STRIDE), wp, lane);
            P1BAR();
            if (tid == 0) sts_rel_cta(c_u1, ow + 3);
        }
        if (tid == 0) stg_rel(inflag, 0);        // replay-safe reset (sole reader)
    } else if (tid < 192) {
        // --------- P2 (wid 3-5): u2 = Wih2 x h1 (ring) ---------
        const int jj = tid - 96;
        const int wp = jj >> 5;
        uint32_t aH[2][6][4], aL[2][6][4];
        fill_afrags(wih2, wp, lane, aH, aL);
        const uint32_t bladdr = (uint32_t)((lane & 7) * 208 + ((lane >> 3) & 1) * 16);
        const uint32_t b0 = dsm + L_BS2, b1 = dsm + L_BS2 + 3328;
        float t8[8];

        SSPIN(c_r1, 8);
        #pragma unroll
        for (int r = 0; r < 8; r++) t8[r] = lds_f32(ring + (uint32_t)(r * 384 + jj * 4));
        pack8(b0, jj, t8); P2BAR();
        { float cfr[2][4] = {{0,0,0,0},{0,0,0,0}};
          mma_block(cfr, b0, bladdr, aH, aL); store_cfr(cfr, u2, wp, lane); }
        SSPIN(c_r1, 16);
        #pragma unroll
        for (int r = 0; r < 8; r++) t8[r] = lds_f32(ring + (uint32_t)((8 + r) * 384 + jj * 4));
        pack8(b1, jj, t8); P2BAR();
        { float cfr[2][4] = {{0,0,0,0},{0,0,0,0}};
          mma_block(cfr, b1, bladdr, aH, aL); store_cfr(cfr, u2 + U_STRIDE, wp, lane); }
        P2BAR();
        if (tid == 96) { sts_rel_cta(c_u2, 2); sts_rel_cta(c_p2, 16); }

        for (int ow = 0; ow < 62; ++ow) {
            const int s0 = 8 * ow + 16;
            SSPIN(c_r1, s0 + 8);
            #pragma unroll
            for (int r = 0; r < 8; r++)
                t8[r] = lds_f32(ring + (uint32_t)((((s0 + r) & 31)) * 384 + jj * 4));
            const uint32_t buf = (ow & 1) ? b1 : b0;
            pack8(buf, jj, t8); P2BAR();
            float cfr[2][4] = {{0,0,0,0},{0,0,0,0}};
            mma_block(cfr, buf, bladdr, aH, aL);
            SSPIN(c_r2, 8 * ow);
            store_cfr(cfr, u2 + (uint32_t)(((ow + 2) % 3) * U_STRIDE), wp, lane);
            P2BAR();
            if (tid == 96) { sts_rel_cta(c_u2, ow + 3); sts_rel_cta(c_p2, s0 + 8); }
        }
    } else if (tid < 288) {
        // --------- R2 (wid 6-8): h2 recurrence + FC head ---------
        const int j = tid - 192;
        ull w[48];
        {
            const float* wr = whh2 + j * H_DIM;
            #pragma unroll
            for (int q = 0; q < 48; q++) w[q] = pack2(__ldg(wr + 2 * q), __ldg(wr + 2 * q + 1));
        }
        const float bias = __ldg(bih2 + j) + __ldg(bhh2 + j);
        const uint32_t dst_j = hb2 + (uint32_t)(j * 4);

        for (int w2 = 0; w2 < 64; ++w2) {
            SSPIN(c_u2, w2 + 1);
            const uint32_t ublk = u2 + (uint32_t)((w2 % 3) * U_STRIDE + j * 36);
            float ur[8];
            #pragma unroll
            for (int si = 0; si < 8; ++si) ur[si] = lds_f32(ublk + (uint32_t)(si * 4));
            #pragma unroll
            for (int si = 0; si < 8; ++si) {
                float d = dot96(hb2 + (uint32_t)(((si & 1) ^ 1) * 384), w);
                float hv = fast_tanh(d + ur[si] + bias);
                sts_f32(dst_j + (uint32_t)((si & 1) * 384), hv);
                BARR2();
            }
            if (j == 0) sts_rel_cta(c_r2, 8 * w2 + 8);
        }
        // FC head: out[b] = h2[511].fc_w + fc_b (parity 1)
        sts_f32(dsm + L_SRED + (uint32_t)(j * 4),
                lds_f32(hb2 + (uint32_t)(384 + j * 4)) * __ldg(fcw + j));
        asm volatile("bar.sync 6, 96;" ::: "memory");
        if (tid == 192) {
            float s = __ldg(fcb);
            #pragma unroll
            for (int k = 0; k < H_DIM; k++) s += lds_f32(dsm + L_SRED + (uint32_t)(k * 4));
            out[b] = s;
        }
    } else {
        // --------- R1 (wid 9-11): h1 recurrence -> ring ---------
        const int j = tid - 288;
        ull w[48];
        {
            const float* wr = whh1 + j * H_DIM;
            #pragma unroll
            for (int q = 0; q < 48; q++) w[q] = pack2(__ldg(wr + 2 * q), __ldg(wr + 2 * q + 1));
        }
        const float bias = __ldg(bih1 + j) + __ldg(bhh1 + j);
        const uint32_t ring_j = ring + (uint32_t)(j * 4);

        for (int w1 = 0; w1 < 64; ++w1) {
            SSPIN(c_u1, w1 + 1);
            SSPIN(c_p2, 8 * w1 - 24);
            const uint32_t ublk = u1 + (uint32_t)((w1 % 3) * U_STRIDE + j * 36);
            float ur[8];
            #pragma unroll
            for (int si = 0; si < 8; ++si) ur[si] = lds_f32(ublk + (uint32_t)(si * 4));
            #pragma unroll
            for (int si = 0; si < 8; ++si) {
                const int v = 8 * w1 + si;
                float d = dot96(ring + (uint32_t)(((v + 31) & 31) * 384), w);
                float hv = fast_tanh(d + ur[si] + bias);
                sts_f32(ring_j + (uint32_t)((v & 31) * 384), hv);
                BARR1();
            }
            if (j == 0) sts_rel_cta(c_r1, 8 * w1 + 8);
        }
    }
}

extern "C" void kernel_launch(void* const* d_in, const int* in_sizes, int n_in,
                              void* d_out, int out_size) {
    const float* x     = (const float*)d_in[0];
    const float* w_ih0 = (const float*)d_in[1];
    const float* w_hh0 = (const float*)d_in[2];
    const float* b_ih0 = (const float*)d_in[3];
    const float* b_hh0 = (const float*)d_in[4];
    const float* w_ih1 = (const float*)d_in[5];
    const float* w_hh1 = (const float*)d_in[6];
    const float* b_ih1 = (const float*)d_in[7];
    const float* b_hh1 = (const float*)d_in[8];
    const float* w_ih2 = (const float*)d_in[9];
    const float* w_hh2 = (const float*)d_in[10];
    const float* b_ih2 = (const float*)d_in[11];
    const float* b_hh2 = (const float*)d_in[12];
    const float* fc_w  = (const float*)d_in[13];
    const float* fc_b  = (const float*)d_in[14];
    float* out = (float*)d_out;

    cudaFuncSetAttribute(rnn_all, cudaFuncAttributeMaxDynamicSharedMemorySize, SCAN_SMEM);
    rnn_all<<<148, 384, SCAN_SMEM>>>(x,
                                     w_ih0, w_hh0, b_ih0, b_hh0,
                                     w_ih1, w_hh1, b_ih1, b_hh1,
                                     w_ih2, w_hh2, b_ih2, b_hh2,
                                     fc_w, fc_b, out);
}

// round 16
// speedup vs baseline: 3.0095x; 3.0095x over previous
#include <cuda_runtime.h>
#include <cuda_bf16.h>
#include <cstdint>

#define I_DIM 2048
#define H_DIM 96
#define B_DIM 64
#define T_DIM 512

typedef unsigned long long ull;

// ============================ generic helpers ==============================

__device__ __forceinline__ void fma2(ull &d, ull a, ull b) {
    asm("fma.rn.f32x2 %0, %1, %2, %0;" : "+l"(d) : "l"(a), "l"(b));
}
__device__ __forceinline__ ull pack2(float lo, float hi) {
    ull v; asm("mov.b64 %0, {%1, %2};" : "=l"(v) : "f"(lo), "f"(hi)); return v;
}
__device__ __forceinline__ float fast_tanh(float x) {
    float e = __expf(2.0f * x);
    return 1.0f - __fdividef(2.0f, e + 1.0f);
}
__device__ __forceinline__ uint32_t smem_u32(const void* p) {
    uint32_t a;
    asm("{ .reg .u64 t; cvta.to.shared.u64 t, %1; cvt.u32.u64 %0, t; }" : "=r"(a) : "l"(p));
    return a;
}
__device__ __forceinline__ void lds_v2u64(ull &x, ull &y, uint32_t a) {
    asm volatile("ld.shared.v2.b64 {%0,%1}, [%2];" : "=l"(x), "=l"(y) : "r"(a));
}
__device__ __forceinline__ void sts_f32(uint32_t a, float v) {
    asm volatile("st.shared.f32 [%0], %1;" :: "r"(a), "f"(v) : "memory");
}
__device__ __forceinline__ void sts_u16(uint32_t a, uint16_t v) {
    asm volatile("st.shared.u16 [%0], %1;" :: "r"(a), "h"(v) : "memory");
}
__device__ __forceinline__ float lds_f32(uint32_t a) {
    float v; asm volatile("ld.shared.f32 %0, [%1];" : "=f"(v) : "r"(a)); return v;
}
__device__ __forceinline__ float hsum4x(ull a0, ull a1, ull a2, ull a3) {
    ull t, u, v;
    asm("add.rn.f32x2 %0, %1, %2;" : "=l"(t) : "l"(a0), "l"(a1));
    asm("add.rn.f32x2 %0, %1, %2;" : "=l"(u) : "l"(a2), "l"(a3));
    asm("add.rn.f32x2 %0, %1, %2;" : "=l"(v) : "l"(t), "l"(u));
    float lo, hi; asm("mov.b64 {%0,%1}, %2;" : "=f"(lo), "=f"(hi) : "l"(v));
    return lo + hi;
}
// cross-CTA flags (gpu scope)
__device__ __forceinline__ int ldg_acq(const int* p) {
    int v; asm volatile("ld.global.acquire.gpu.u32 %0, [%1];" : "=r"(v) : "l"(p) : "memory");
    return v;
}
__device__ __forceinline__ void stg_rel(int* p, int v) {
    asm volatile("membar.gl;" ::: "memory");
    asm volatile("st.global.release.gpu.u32 [%0], %1;" :: "l"(p), "r"(v) : "memory");
}
#define GPOLL(p, val) do { \
    if (ldg_acq(p) < (val)) { while (ldg_acq(p) < (val)) __nanosleep(64); } \
} while (0)
// intra-CTA flags (smem, cta scope) — pure spin, no nanosleep (smem-local)
__device__ __forceinline__ int lds_acq_cta(uint32_t a) {
    int v; asm volatile("ld.acquire.cta.shared.u32 %0, [%1];" : "=r"(v) : "r"(a) : "memory");
    return v;
}
__device__ __forceinline__ void sts_rel_cta(uint32_t a, int v) {
    asm volatile("st.release.cta.shared.u32 [%0], %1;" :: "r"(a), "r"(v) : "memory");
}
#define SSPIN(addr, val) do { \
    while (lds_acq_cta(addr) < (val)) { } \
} while (0)

// 96-float dot: broadcast LDS from src, weights in wreg[48] (ull pairs).
__device__ __forceinline__ float dot96(uint32_t src, const ull* wreg) {
    ull a0 = 0, a1 = 0, a2 = 0, a3 = 0;
    #pragma unroll
    for (int k = 0; k < 24; k++) {
        ull vx, vy; lds_v2u64(vx, vy, src + 16 * k);
        if (k & 1) { fma2(a2, wreg[2 * k], vx); fma2(a3, wreg[2 * k + 1], vy); }
        else       { fma2(a0, wreg[2 * k], vx); fma2(a1, wreg[2 * k + 1], vy); }
    }
    return hsum4x(a0, a1, a2, a3);
}

// ======================= mma.sync / ldmatrix helpers =======================

__device__ __forceinline__ void ldsm_x4(uint32_t &r0, uint32_t &r1, uint32_t &r2,
                                        uint32_t &r3, uint32_t addr) {
    asm volatile("ldmatrix.sync.aligned.m8n8.x4.shared.b16 {%0,%1,%2,%3}, [%4];"
                 : "=r"(r0), "=r"(r1), "=r"(r2), "=r"(r3) : "r"(addr));
}
__device__ __forceinline__ void ldsm_x2(uint32_t &r0, uint32_t &r1, uint32_t addr) {
    asm volatile("ldmatrix.sync.aligned.m8n8.x2.shared.b16 {%0,%1}, [%2];"
                 : "=r"(r0), "=r"(r1) : "r"(addr));
}
__device__ __forceinline__ void mma16816(float* c, const uint32_t* a, const uint32_t* b) {
    asm volatile("mma.sync.aligned.m16n8k16.row.col.f32.bf16.bf16.f32 "
                 "{%0,%1,%2,%3}, {%4,%5,%6,%7}, {%8,%9}, {%0,%1,%2,%3};"
                 : "+f"(c[0]), "+f"(c[1]), "+f"(c[2]), "+f"(c[3])
                 : "r"(a[0]), "r"(a[1]), "r"(a[2]), "r"(a[3]), "r"(b[0]), "r"(b[1]));
}
__device__ __forceinline__ void cvt_hilo(float4 v, uint2 &hp, uint2 &lp) {
    __nv_bfloat162 h0 = __float22bfloat162_rn(make_float2(v.x, v.y));
    __nv_bfloat162 h1 = __float22bfloat162_rn(make_float2(v.z, v.w));
    float2 f0 = __bfloat1622float2(h0), f1 = __bfloat1622float2(h1);
    __nv_bfloat162 l0 = __float22bfloat162_rn(make_float2(v.x - f0.x, v.y - f0.y));
    __nv_bfloat162 l1 = __float22bfloat162_rn(make_float2(v.z - f1.x, v.w - f1.y));
    hp = make_uint2(*(uint32_t*)&h0, *(uint32_t*)&h1);
    lp = make_uint2(*(uint32_t*)&l0, *(uint32_t*)&l1);
}
__device__ __forceinline__ void cvt_hilo2(float2 v, uint32_t &hp, uint32_t &lp) {
    __nv_bfloat162 h = __float22bfloat162_rn(v);
    float2 f = __bfloat1622float2(h);
    __nv_bfloat162 l = __float22bfloat162_rn(make_float2(v.x - f.x, v.y - f.y));
    hp = *(uint32_t*)&h; lp = *(uint32_t*)&l;
}
__device__ __forceinline__ void cvt_hilo1(float v, uint16_t &hb, uint16_t &lb) {
    __nv_bfloat16 h = __float2bfloat16(v);
    float f = __bfloat162float(h);
    __nv_bfloat16 l = __float2bfloat16(v - f);
    hb = *(uint16_t*)&h; lb = *(uint16_t*)&lb, lb = *(uint16_t*)&l;
}

// P-group building blocks -----------------------------------------------------

__device__ __forceinline__ void fill_afrags(const float* wih, int wp, int lane,
                                            uint32_t (&aH)[2][6][4], uint32_t (&aL)[2][6][4]) {
    const int q = lane >> 2, kq = 2 * (lane & 3);
    #pragma unroll
    for (int mt = 0; mt < 2; ++mt) {
        const int r0 = 32 * wp + 16 * mt + q;
        #pragma unroll
        for (int kc = 0; kc < 6; ++kc) {
            const int k0 = 16 * kc + kq;
            float2 v00 = *(const float2*)(wih + r0 * H_DIM + k0);
            float2 v10 = *(const float2*)(wih + (r0 + 8) * H_DIM + k0);
            float2 v01 = *(const float2*)(wih + r0 * H_DIM + k0 + 8);
            float2 v11 = *(const float2*)(wih + (r0 + 8) * H_DIM + k0 + 8);
            cvt_hilo2(v00, aH[mt][kc][0], aL[mt][kc][0]);
            cvt_hilo2(v10, aH[mt][kc][1], aL[mt][kc][1]);
            cvt_hilo2(v01, aH[mt][kc][2], aL[mt][kc][2]);
            cvt_hilo2(v11, aH[mt][kc][3], aL[mt][kc][3]);
        }
    }
}
__device__ __forceinline__ void pack8(uint32_t buf, int jj, const float* v8) {
    #pragma unroll
    for (int r = 0; r < 8; r++) {
        __nv_bfloat16 h = __float2bfloat16(v8[r]);
        float f = __bfloat162float(h);
        __nv_bfloat16 l = __float2bfloat16(v8[r] - f);
        sts_u16(buf + (uint32_t)(r * 208 + jj * 2), *(uint16_t*)&h);
        sts_u16(buf + 1664 + (uint32_t)(r * 208 + jj * 2), *(uint16_t*)&l);
    }
}
__device__ __forceinline__ void mma_block(float (&cfr)[2][4], uint32_t buf, uint32_t bladdr,
                                          const uint32_t (&aH)[2][6][4],
                                          const uint32_t (&aL)[2][6][4]) {
    #pragma unroll
    for (int kc = 0; kc < 6; ++kc) {
        uint32_t bh[2], bl[2];
        ldsm_x2(bh[0], bh[1], buf + bladdr + kc * 32);
        ldsm_x2(bl[0], bl[1], buf + 1664 + bladdr + kc * 32);
        #pragma unroll
        for (int mt = 0; mt < 2; ++mt) {
            mma16816(cfr[mt], aH[mt][kc], bh);
            mma16816(cfr[mt], aH[mt][kc], bl);
            mma16816(cfr[mt], aL[mt][kc], bh);
        }
    }
}
// scalar stores (36B row stride is 4-mod-8 on odd rows)
__device__ __forceinline__ void store_cfr(const float (&cfr)[2][4], uint32_t ublk,
                                          int wp, int lane) {
    #pragma unroll
    for (int mt = 0; mt < 2; ++mt) {
        const int row = 32 * wp + 16 * mt + (lane >> 2);
        const uint32_t a0 = ublk + (uint32_t)(row * 36 + (lane & 3) * 8);
        sts_f32(a0, cfr[mt][0]);
        sts_f32(a0 + 4, cfr[mt][1]);
        sts_f32(a0 + 288, cfr[mt][2]);
        sts_f32(a0 + 292, cfr[mt][3]);
    }
}

// ===================== global scratch (no allocations) =====================
__device__ float g_xproj[(size_t)B_DIM * T_DIM * H_DIM];
__device__ float g_h0[(size_t)B_DIM * T_DIM * H_DIM];
__device__ int   g_prog[2 * B_DIM];

// ===========================================================================
// Kernel 1: xproj = x @ w_ih0^T + b_ih0, HMMA bf16 3-split.
// M-tile 256, grid 128, occ 1 (the proven r11 config).
// ===========================================================================
#define ROWB 80
#define SM_BIAS 0
#define SM_AHI  512
#define SM_ALO  (512 + 20480)
#define SM_BHI  (512 + 40960)
#define SM_BLO  (512 + 40960 + 7680)
#define GEMM_SMEM (512 + 40960 + 15360)   // 56832 bytes

__global__ __launch_bounds__(256, 1) void xproj_gemm(const float* __restrict__ X,
                                                     const float* __restrict__ W,
                                                     const float* __restrict__ bias)
{
    extern __shared__ char smem[];
    float* sbias = (float*)(smem + SM_BIAS);
    const int tid = threadIdx.x, lane = tid & 31, warp = tid >> 5;
    const int rowbase = blockIdx.x * 256;
    const int m_warp = (warp & 3) * 64;
    const int n_warp = (warp >> 2) * 48;

    if (blockIdx.x == 0 && tid < 2 * B_DIM) g_prog[tid] = 0;
    if (tid < H_DIM) sbias[tid] = __ldg(bias + tid);

    const int g = lane >> 3, r = lane & 7;
    const uint32_t lane_off = (uint32_t)((((g & 1) << 3) + r) * ROWB + ((g >> 1) << 4));
    const uint32_t sb = smem_u32(smem);
    const uint32_t aHiB = sb + SM_AHI + (uint32_t)m_warp * ROWB + lane_off;
    const uint32_t aLoB = sb + SM_ALO + (uint32_t)m_warp * ROWB + lane_off;
    const uint32_t bHiB = sb + SM_BHI + (uint32_t)n_warp * ROWB + lane_off;
    const uint32_t bLoB = sb + SM_BLO + (uint32_t)n_warp * ROWB + lane_off;

    float acc[4][6][4];
    #pragma unroll
    for (int mt = 0; mt < 4; mt++)
        #pragma unroll
        for (int nt = 0; nt < 6; nt++)
            #pragma unroll
            for (int i = 0; i < 4; i++) acc[mt][nt][i] = 0.f;

    float4 sa[8], sw[3];

    auto load_stage = [&](int k0) {
        #pragma unroll
        for (int it = 0; it < 8; ++it) {
            int f = tid + it * 256;
            sa[it] = *(const float4*)(X + (size_t)(rowbase + (f >> 3)) * I_DIM + k0 + ((f & 7) << 2));
        }
        #pragma unroll
        for (int it = 0; it < 3; ++it) {
            int f = tid + it * 256;
            sw[it] = *(const float4*)(W + (size_t)(f >> 3) * I_DIM + k0 + ((f & 7) << 2));
        }
    };
    auto store_stage = [&]() {
        #pragma unroll
        for (int it = 0; it < 8; ++it) {
            int f = tid + it * 256;
            int off = (f >> 3) * ROWB + ((f & 7) << 3);
            uint2 hp, lp; cvt_hilo(sa[it], hp, lp);
            *(uint2*)(smem + SM_AHI + off) = hp;
            *(uint2*)(smem + SM_ALO + off) = lp;
        }
        #pragma unroll
        for (int it = 0; it < 3; ++it) {
            int f = tid + it * 256;
            int off = (f >> 3) * ROWB + ((f & 7) << 3);
            uint2 hp, lp; cvt_hilo(sw[it], hp, lp);
            *(uint2*)(smem + SM_BHI + off) = hp;
            *(uint2*)(smem + SM_BLO + off) = lp;
        }
    };

    load_stage(0);
    store_stage();
    __syncthreads();

    const int NC = I_DIM / 32;   // 64
    for (int c = 0; c < NC; ++c) {
        if (c + 1 < NC) load_stage((c + 1) * 32);

        #pragma unroll
        for (int s = 0; s < 2; ++s) {
            uint32_t ah[4][4], al[4][4], bh[6][2], bl[6][2];
            #pragma unroll
            for (int mt = 0; mt < 4; ++mt) {
                ldsm_x4(ah[mt][0], ah[mt][1], ah[mt][2], ah[mt][3], aHiB + mt * (16 * ROWB) + s * 32);
                ldsm_x4(al[mt][0], al[mt][1], al[mt][2], al[mt][3], aLoB + mt * (16 * ROWB) + s * 32);
            }
            #pragma unroll
            for (int np = 0; np < 3; ++np) {
                uint32_t r0, r1, r2, r3;
                ldsm_x4(r0, r1, r2, r3, bHiB + np * (16 * ROWB) + s * 32);
                bh[2 * np][0] = r0; bh[2 * np + 1][0] = r1;
                bh[2 * np][1] = r2; bh[2 * np + 1][1] = r3;
                ldsm_x4(r0, r1, r2, r3, bLoB + np * (16 * ROWB) + s * 32);
                bl[2 * np][0] = r0; bl[2 * np + 1][0] = r1;
                bl[2 * np][1] = r2; bl[2 * np + 1][1] = r3;
            }
            #pragma unroll
            for (int mt = 0; mt < 4; ++mt)
                #pragma unroll
                for (int nt = 0; nt < 6; ++nt) {
                    mma16816(acc[mt][nt], ah[mt], bh[nt]);
                    mma16816(acc[mt][nt], ah[mt], bl[nt]);
                    mma16816(acc[mt][nt], al[mt], bh[nt]);
                }
        }
        __syncthreads();
        if (c + 1 < NC) { store_stage(); }
        __syncthreads();
    }

    #pragma unroll
    for (int nt = 0; nt < 6; ++nt) {
        int col = n_warp + nt * 8 + (lane & 3) * 2;
        float b0 = sbias[col], b1 = sbias[col + 1];
        #pragma unroll
        for (int mt = 0; mt < 4; ++mt) {
            int row0 = rowbase + m_warp + mt * 16 + (lane >> 2);
            float2 v0 = make_float2(acc[mt][nt][0] + b0, acc[mt][nt][1] + b1);
            float2 v1 = make_float2(acc[mt][nt][2] + b0, acc[mt][nt][3] + b1);
            *(float2*)(g_xproj + (size_t)row0 * H_DIM + col) = v0;
            *(float2*)(g_xproj + (size_t)(row0 + 8) * H_DIM + col) = v1;
        }
    }
}

// ===========================================================================
// Kernel 2: scan (proven r11 structure + u-prefetch + pure-spin SSPIN).
// Grid 128. Blocks 0-63: layer 0. Blocks 64-127: layers 1+2:
//   R1 (0-95)    : h1 recurrence. bar 2 with P1. h1 -> smem ring (32 slots).
//   P1 (96-191)  : u1 = Wih1 x h0-stream (global, GPOLL) via HMMA. bar 2.
//   R2 (192-287) : h2 recurrence. bar 3 with P2. FC head at end.
//   P2 (288-383) : u2 = Wih2 x h1 (smem ring). bar 3.
// ===========================================================================
#define L_H1   0
#define L_H2   768
#define L_RING 1536
#define L_U1   13824
#define L_U2   24192
#define L_BS1  34560
#define L_BS2  41216
#define L_SRED 47872
#define L_CNT  48256
#define SCAN_SMEM 48320
#define U_STRIDE 3456

#define BAR1() asm volatile("bar.sync 1, 96;"  ::: "memory")
#define BAR2() asm volatile("bar.sync 2, 192;" ::: "memory")
#define BAR3() asm volatile("bar.sync 3, 192;" ::: "memory")
#define P1BAR() asm volatile("bar.sync 4, 96;" ::: "memory")
#define P2BAR() asm volatile("bar.sync 5, 96;" ::: "memory")

__global__ __launch_bounds__(384, 1) void rnn_layer(
    const float* __restrict__ whh0, const float* __restrict__ bhh0,
    const float* __restrict__ wih1, const float* __restrict__ whh1,
    const float* __restrict__ bih1, const float* __restrict__ bhh1,
    const float* __restrict__ wih2, const float* __restrict__ whh2,
    const float* __restrict__ bih2, const float* __restrict__ bhh2,
    const float* __restrict__ fcw,  const float* __restrict__ fcb,
    float* __restrict__ out)
{
    extern __shared__ char dyns[];
    const uint32_t dsm = smem_u32(dyns);
    const int tid = threadIdx.x;
    const int lane = tid & 31;

    if (blockIdx.x < 64) {
        // ============================ LAYER 0 ============================
        const int b = blockIdx.x;
        const size_t soff = (size_t)b * T_DIM * H_DIM;
        if (tid < 192) sts_f32(dsm + tid * 4, 0.f);
        __syncthreads();
        if (tid >= 96) return;

        const int j = tid;
        ull w[48];
        {
            const float* wr = whh0 + j * H_DIM;
            #pragma unroll
            for (int q = 0; q < 48; q++) w[q] = pack2(__ldg(wr + 2 * q), __ldg(wr + 2 * q + 1));
        }
        const float bias = __ldg(bhh0 + j);
        const float* xpp = g_xproj + soff + j;
        float* outstream = g_h0 + soff;
        int* flag = &g_prog[b];

        float xc[8], xn[8];
        #pragma unroll
        for (int r = 0; r < 8; r++) xc[r] = __ldg(xpp + (size_t)r * H_DIM);
        #pragma unroll
        for (int r = 0; r < 8; r++) xn[r] = __ldg(xpp + (size_t)(8 + r) * H_DIM);

        const uint32_t dst_j = dsm + (uint32_t)(j * 4);
        for (int ow = 0; ow < 64; ++ow) {
            #pragma unroll
            for (int si = 0; si < 8; ++si) {
                const int v = 8 * ow + si;
                float d = dot96(dsm + (uint32_t)(((si & 1) ^ 1) * 384), w);
                float hv = fast_tanh(d + xc[si] + bias);
                sts_f32(dst_j + (uint32_t)((si & 1) * 384), hv);
                outstream[(size_t)v * H_DIM + j] = hv;
                BAR1();
            }
            if (j == 0) stg_rel(flag, 8 * ow + 8);
            #pragma unroll
            for (int r = 0; r < 8; r++) xc[r] = xn[r];
            #pragma unroll
            for (int r = 0; r < 8; r++) {
                int t = 8 * ow + 16 + r; if (t > T_DIM - 1) t = T_DIM - 1;
                xn[r] = __ldg(xpp + (size_t)t * H_DIM);
            }
        }
        return;
    }

    // ============================ LAYERS 1+2 ============================
    const int b = blockIdx.x - 64;
    const size_t soff = (size_t)b * T_DIM * H_DIM;
    const uint32_t hb1 = dsm + L_H1, hb2 = dsm + L_H2, ring = dsm + L_RING;
    const uint32_t u1 = dsm + L_U1, u2 = dsm + L_U2;
    const uint32_t c_r1 = dsm + L_CNT, c_p2 = dsm + L_CNT + 4;

    if (tid < 192) { sts_f32(hb1 + tid * 4, 0.f); sts_f32(hb2 + tid * 4, 0.f); }
    if (tid == 0) { sts_f32(c_r1, 0.f); sts_f32(c_p2, 0.f); }
    __syncthreads();

    if (tid < 96) {
        // ------------------------------ R1 ------------------------------
        const int j = tid;
        ull w[48];
        {
            const float* wr = whh1 + j * H_DIM;
            #pragma unroll
            for (int q = 0; q < 48; q++) w[q] = pack2(__ldg(wr + 2 * q), __ldg(wr + 2 * q + 1));
        }
        const float bias = __ldg(bih1 + j) + __ldg(bhh1 + j);
        const uint32_t dst_j = hb1 + (uint32_t)(j * 4);
        const uint32_t ring_j = ring + (uint32_t)(j * 4);

        for (int w1 = 0; w1 < 64; ++w1) {
            SSPIN(c_p2, 8 * w1 - 24);                        // ring backpressure
            const uint32_t ublk = u1 + (uint32_t)((w1 % 3) * U_STRIDE + j * 36);
            float ur[8];
            #pragma unroll
            for (int si = 0; si < 8; ++si) ur[si] = lds_f32(ublk + (uint32_t)(si * 4));
            #pragma unroll
            for (int si = 0; si < 8; ++si) {
                const int v = 8 * w1 + si;
                float d = dot96(hb1 + (uint32_t)(((si & 1) ^ 1) * 384), w);
                float hv = fast_tanh(d + ur[si] + bias);
                sts_f32(dst_j + (uint32_t)((si & 1) * 384), hv);
                sts_f32(ring_j + (uint32_t)((v & 31) * 384), hv);
                BAR2();
            }
            if (j == 0) sts_rel_cta(c_r1, 8 * w1 + 8);
        }
    } else if (tid < 192) {
        // ------------------------------ P1 ------------------------------
        const int jj = tid - 96;
        const int wp = jj >> 5;
        uint32_t aH[2][6][4], aL[2][6][4];
        fill_afrags(wih1, wp, lane, aH, aL);
        const uint32_t bladdr = (uint32_t)((lane & 7) * 208 + ((lane >> 3) & 1) * 16);
        const uint32_t b0 = dsm + L_BS1, b1 = dsm + L_BS1 + 3328;
        const float* instream = g_h0 + soff;
        const int* inflag = &g_prog[b];

        float lr[8], t8[8];
        GPOLL(inflag, 24);
        #pragma unroll
        for (int r = 0; r < 8; r++) t8[r] = instream[(size_t)r * H_DIM + jj];
        pack8(b0, jj, t8); P1BAR();
        { float cfr[2][4] = {{0,0,0,0},{0,0,0,0}};
          mma_block(cfr, b0, bladdr, aH, aL);
          store_cfr(cfr, u1, wp, lane); }
        #pragma unroll
        for (int r = 0; r < 8; r++) t8[r] = instream[(size_t)(8 + r) * H_DIM + jj];
        pack8(b1, jj, t8); P1BAR();
        { float cfr[2][4] = {{0,0,0,0},{0,0,0,0}};
          mma_block(cfr, b1, bladdr, aH, aL);
          store_cfr(cfr, u1 + U_STRIDE, wp, lane); }
        #pragma unroll
        for (int r = 0; r < 8; r++) lr[r] = instream[(size_t)(16 + r) * H_DIM + jj];

        for (int ow = 0; ow < 64; ++ow) {
            const bool prod = (8 * ow + 16 < T_DIM);
            const uint32_t buf = (ow & 1) ? b1 : b0;
            float cfr[2][4] = {{0,0,0,0},{0,0,0,0}};
            if (prod) {
                pack8(buf, jj, lr); P1BAR();
                #pragma unroll
                for (int kc = 0; kc < 3; ++kc) {
                    uint32_t bhv[2], blv[2];
                    ldsm_x2(bhv[0], bhv[1], buf + bladdr + kc * 32);
                    ldsm_x2(blv[0], blv[1], buf + 1664 + bladdr + kc * 32);
                    #pragma unroll
                    for (int mt = 0; mt < 2; ++mt) {
                        mma16816(cfr[mt], aH[mt][kc], bhv);
                        mma16816(cfr[mt], aH[mt][kc], blv);
                        mma16816(cfr[mt], aL[mt][kc], bhv);
                    }
                }
            }
            BAR2();
            if (prod) {
                #pragma unroll
                for (int kc = 3; kc < 6; ++kc) {
                    uint32_t bhv[2], blv[2];
                    ldsm_x2(bhv[0], bhv[1], buf + bladdr + kc * 32);
                    ldsm_x2(blv[0], blv[1], buf + 1664 + bladdr + kc * 32);
                    #pragma unroll
                    for (int mt = 0; mt < 2; ++mt) {
                        mma16816(cfr[mt], aH[mt][kc], bhv);
                        mma16816(cfr[mt], aH[mt][kc], blv);
                        mma16816(cfr[mt], aL[mt][kc], bhv);
                    }
                }
                store_cfr(cfr, u1 + (uint32_t)(((ow + 2) % 3) * U_STRIDE), wp, lane);
            }
            BAR2();
            const bool fetch = (8 * ow + 24 < T_DIM);
            if (fetch) {
                int need = 8 * ow + 32; if (need > T_DIM) need = T_DIM;
                GPOLL(inflag, need);
                #pragma unroll
                for (int r = 0; r < 4; r++) lr[r] = instream[(size_t)(8 * ow + 24 + r) * H_DIM + jj];
            }
            BAR2();
            if (fetch) {
                #pragma unroll
                for (int r = 4; r < 8; r++) lr[r] = instream[(size_t)(8 * ow + 24 + r) * H_DIM + jj];
            }
            BAR2(); BAR2(); BAR2(); BAR2(); BAR2();
        }
    } else if (tid < 288) {
        // ------------------------------ R2 ------------------------------
        const int j = tid - 192;
        ull w[48];
        {
            const float* wr = whh2 + j * H_DIM;
            #pragma unroll
            for (int q = 0; q < 48; q++) w[q] = pack2(__ldg(wr + 2 * q), __ldg(wr + 2 * q + 1));
        }
        const float bias = __ldg(bih2 + j) + __ldg(bhh2 + j);
        const uint32_t dst_j = hb2 + (uint32_t)(j * 4);

        for (int w2 = 0; w2 < 64; ++w2) {
            const uint32_t ublk = u2 + (uint32_t)((w2 % 3) * U_STRIDE + j * 36);
            float ur[8];
            #pragma unroll
            for (int si = 0; si < 8; ++si) ur[si] = lds_f32(ublk + (uint32_t)(si * 4));
            #pragma unroll
            for (int si = 0; si < 8; ++si) {
                float d = dot96(hb2 + (uint32_t)(((si & 1) ^ 1) * 384), w);
                float hv = fast_tanh(d + ur[si] + bias);
                sts_f32(dst_j + (uint32_t)((si & 1) * 384), hv);
                BAR3();
            }
        }
        // FC head: out[b] = h2[511].fc_w + fc_b (parity 1)
        sts_f32(dsm + L_SRED + (uint32_t)(j * 4),
                lds_f32(hb2 + (uint32_t)(384 + j * 4)) * __ldg(fcw + j));
        asm volatile("bar.sync 6, 96;" ::: "memory");
        if (tid == 192) {
            float s = __ldg(fcb);
            #pragma unroll
            for (int k = 0; k < H_DIM; k++) s += lds_f32(dsm + L_SRED + (uint32_t)(k * 4));
            out[b] = s;
        }
    } else {
        // ------------------------------ P2 ------------------------------
        const int jj = tid - 288;
        const int wp = jj >> 5;
        uint32_t aH[2][6][4], aL[2][6][4];
        fill_afrags(wih2, wp, lane, aH, aL);
        const uint32_t bladdr = (uint32_t)((lane & 7) * 208 + ((lane >> 3) & 1) * 16);
        const uint32_t b0 = dsm + L_BS2, b1 = dsm + L_BS2 + 3328;

        float lr[8], t8[8];
        SSPIN(c_r1, 24);
        #pragma unroll
        for (int r = 0; r < 8; r++) t8[r] = lds_f32(ring + (uint32_t)(r * 384 + jj * 4));
        pack8(b0, jj, t8); P2BAR();
        { float cfr[2][4] = {{0,0,0,0},{0,0,0,0}};
          mma_block(cfr, b0, bladdr, aH, aL);
          store_cfr(cfr, u2, wp, lane); }
        #pragma unroll
        for (int r = 0; r < 8; r++) t8[r] = lds_f32(ring + (uint32_t)((8 + r) * 384 + jj * 4));
        pack8(b1, jj, t8); P2BAR();
        { float cfr[2][4] = {{0,0,0,0},{0,0,0,0}};
          mma_block(cfr, b1, bladdr, aH, aL);
          store_cfr(cfr, u2 + U_STRIDE, wp, lane); }
        #pragma unroll
        for (int r = 0; r < 8; r++) lr[r] = lds_f32(ring + (uint32_t)((16 + r) * 384 + jj * 4));
        P2BAR();
        if (tid == 288) sts_rel_cta(c_p2, 24);

        for (int ow = 0; ow < 64; ++ow) {
            const bool prod = (8 * ow + 16 < T_DIM);
            const uint32_t buf = (ow & 1) ? b1 : b0;
            float cfr[2][4] = {{0,0,0,0},{0,0,0,0}};
            if (prod) {
                pack8(buf, jj, lr); P2BAR();
                #pragma unroll
                for (int kc = 0; kc < 3; ++kc) {
                    uint32_t bhv[2], blv[2];
                    ldsm_x2(bhv[0], bhv[1], buf + bladdr + kc * 32);
                    ldsm_x2(blv[0], blv[1], buf + 1664 + bladdr + kc * 32);
                    #pragma unroll
                    for (int mt = 0; mt < 2; ++mt) {
                        mma16816(cfr[mt], aH[mt][kc], bhv);
                        mma16816(cfr[mt], aH[mt][kc], blv);
                        mma16816(cfr[mt], aL[mt][kc], bhv);
                    }
                }
            }
            BAR3();
            if (prod) {
                #pragma unroll
                for (int kc = 3; kc < 6; ++kc) {
                    uint32_t bhv[2], blv[2];
                    ldsm_x2(bhv[0], bhv[1], buf + bladdr + kc * 32);
                    ldsm_x2(blv[0], blv[1], buf + 1664 + bladdr + kc * 32);
                    #pragma unroll
                    for (int mt = 0; mt < 2; ++mt) {
                        mma16816(cfr[mt], aH[mt][kc], bhv);
                        mma16816(cfr[mt], aH[mt][kc], blv);
                        mma16816(cfr[mt], aL[mt][kc], bhv);
                    }
                }
                store_cfr(cfr, u2 + (uint32_t)(((ow + 2) % 3) * U_STRIDE), wp, lane);
            }
            BAR3();
            const bool fetch = (8 * ow + 24 < T_DIM);
            if (fetch) {
                int need = 8 * ow + 32; if (need > T_DIM) need = T_DIM;
                SSPIN(c_r1, need);
                #pragma unroll
                for (int r = 0; r < 8; r++)
                    lr[r] = lds_f32(ring + (uint32_t)((((8 * ow + 24 + r) & 31)) * 384 + jj * 4));
            }
            BAR3();
            if (fetch && tid == 288) sts_rel_cta(c_p2, 8 * ow + 32);
            BAR3(); BAR3(); BAR3(); BAR3(); BAR3();
        }
    }
}

extern "C" void kernel_launch(void* const* d_in, const int* in_sizes, int n_in,
                              void* d_out, int out_size) {
    const float* x     = (const float*)d_in[0];
    const float* w_ih0 = (const float*)d_in[1];
    const float* w_hh0 = (const float*)d_in[2];
    const float* b_ih0 = (const float*)d_in[3];
    const float* b_hh0 = (const float*)d_in[4];
    const float* w_ih1 = (const float*)d_in[5];
    const float* w_hh1 = (const float*)d_in[6];
    const float* b_ih1 = (const float*)d_in[7];
    const float* b_hh1 = (const float*)d_in[8];
    const float* w_ih2 = (const float*)d_in[9];
    const float* w_hh2 = (const float*)d_in[10];
    const float* b_ih2 = (const float*)d_in[11];
    const float* b_hh2 = (const float*)d_in[12];
    const float* fc_w  = (const float*)d_in[13];
    const float* fc_b  = (const float*)d_in[14];
    float* out = (float*)d_out;

    cudaFuncSetAttribute(xproj_gemm, cudaFuncAttributeMaxDynamicSharedMemorySize, GEMM_SMEM);
    cudaFuncSetAttribute(rnn_layer, cudaFuncAttributeMaxDynamicSharedMemorySize, SCAN_SMEM);
    xproj_gemm<<<(B_DIM * T_DIM) / 256, 256, GEMM_SMEM>>>(x, w_ih0, b_ih0);
    rnn_layer<<<128, 384, SCAN_SMEM>>>(w_hh0, b_hh0,
                                       w_ih1, w_hh1, b_ih1, b_hh1,
                                       w_ih2, w_hh2, b_ih2, b_hh2,
                                       fc_w, fc_b, out);
}